// round 11
// baseline (speedup 1.0000x reference)
#include <cuda_runtime.h>
#include <cstdint>

// ---------------------------------------------------------------------------
// CustomOrientationLoss (R11):
//   fused pack+edge (persistent, occ 6, one grid barrier)  — deletes the
//     pack->edge launch serialization (~5us); edge phase is LTS-RMW-bound and
//     occupancy-insensitive (proven occ 6 == occ 16), so fusion at occ 6 is free.
//   node: cos/angle reduction + fused finalize (unchanged R9 body).
// ---------------------------------------------------------------------------

#define NMAX 100000

__device__ float4 g_P[NMAX];        // (x0,x1,x2,s)
__device__ float4 g_Z[NMAX];        // accumulator (w unused)
__device__ double g_acc[3];         // sum(1-|cos|), sum(ang_deg), count
__device__ unsigned int g_done;     // node last-block counter
__device__ unsigned int g_bar;      // grid barrier counter (reset by node)

// ---------------------------------------------------------------------------
// Persistent pack+edge. All blocks co-resident (launch_bounds(256,6), grid=SM*6).
__global__ __launch_bounds__(256, 6)
void pack_edge_kernel(const float* __restrict__ x,
                      const float* __restrict__ s,
                      const int* __restrict__ ei,
                      int N, int E) {
    const int tid     = blockIdx.x * blockDim.x + threadIdx.x;
    const int nthread = gridDim.x * blockDim.x;

    // ---------------- Phase 1: pack + zero (grid-stride) ----------------
    for (int i = tid; i < N; i += nthread) {
        g_P[i] = make_float4(x[3 * i], x[3 * i + 1], x[3 * i + 2], s[i]);
        g_Z[i] = make_float4(0.f, 0.f, 0.f, 0.f);
    }
    if (tid == 0) {
        g_acc[0] = 0.0; g_acc[1] = 0.0; g_acc[2] = 0.0;
        g_done = 0u;
    }

    // ---------------- Grid barrier (co-resident by construction) --------
    __syncthreads();
    if (threadIdx.x == 0) {
        __threadfence();
        atomicAdd(&g_bar, 1u);
        while (atomicAdd(&g_bar, 0u) < gridDim.x) { __nanosleep(64); }
        __threadfence();
    }
    __syncthreads();

    // ---------------- Phase 2: edge scatter (grid-stride, int2 pairs) ----
    int npair = E >> 1;
    for (int p = tid; p < npair; p += nthread) {
        int2 av = *reinterpret_cast<const int2*>(ei + 2 * p);
        int2 bv = *reinterpret_cast<const int2*>(ei + E + 2 * p);

        float4 Pa0 = __ldg(&g_P[av.x]);
        float4 Pb0 = __ldg(&g_P[bv.x]);
        float4 Pa1 = __ldg(&g_P[av.y]);
        float4 Pb1 = __ldg(&g_P[bv.y]);

        float ds0 = Pb0.w - Pa0.w;
        float c0x = (Pb0.x - Pa0.x) * ds0;
        float c0y = (Pb0.y - Pa0.y) * ds0;
        float c0z = (Pb0.z - Pa0.z) * ds0;
        float ds1 = Pb1.w - Pa1.w;
        float c1x = (Pb1.x - Pa1.x) * ds1;
        float c1y = (Pb1.y - Pa1.y) * ds1;
        float c1z = (Pb1.z - Pa1.z) * ds1;

        asm volatile("red.global.add.v4.f32 [%0], {%1, %2, %3, %4};"
                     :: "l"((float*)&g_Z[av.x]), "f"(c0x), "f"(c0y), "f"(c0z), "f"(0.0f) : "memory");
        asm volatile("red.global.add.v4.f32 [%0], {%1, %2, %3, %4};"
                     :: "l"((float*)&g_Z[bv.x]), "f"(c0x), "f"(c0y), "f"(c0z), "f"(0.0f) : "memory");
        asm volatile("red.global.add.v4.f32 [%0], {%1, %2, %3, %4};"
                     :: "l"((float*)&g_Z[av.y]), "f"(c1x), "f"(c1y), "f"(c1z), "f"(0.0f) : "memory");
        asm volatile("red.global.add.v4.f32 [%0], {%1, %2, %3, %4};"
                     :: "l"((float*)&g_Z[bv.y]), "f"(c1x), "f"(c1y), "f"(c1z), "f"(0.0f) : "memory");
    }
    // odd-E tail
    if ((E & 1) && tid == 0) {
        int e = E - 1;
        int a = ei[e], b = ei[E + e];
        float4 Pa = __ldg(&g_P[a]);
        float4 Pb = __ldg(&g_P[b]);
        float ds = Pb.w - Pa.w;
        float cx = (Pb.x - Pa.x) * ds;
        float cy = (Pb.y - Pa.y) * ds;
        float cz = (Pb.z - Pa.z) * ds;
        asm volatile("red.global.add.v4.f32 [%0], {%1, %2, %3, %4};"
                     :: "l"((float*)&g_Z[a]), "f"(cx), "f"(cy), "f"(cz), "f"(0.0f) : "memory");
        asm volatile("red.global.add.v4.f32 [%0], {%1, %2, %3, %4};"
                     :: "l"((float*)&g_Z[b]), "f"(cx), "f"(cy), "f"(cz), "f"(0.0f) : "memory");
    }
}

// ---------------------------------------------------------------------------
// Node reduction (4 nodes/thread) + fused finalize; resets g_bar for next call.
__global__ void node_kernel(const float* __restrict__ y,
                            const int* __restrict__ mask,
                            int N, float* __restrict__ out) {
    int q = blockIdx.x * blockDim.x + threadIdx.x;
    int nq = N >> 2;

    float l = 0.f, ang = 0.f, c = 0.f;
    const float4* y4 = (const float4*)y;
    const int4*   m4 = (const int4*)mask;

    if (q < nq) {
        float4 a = y4[3 * q + 0];
        float4 b = y4[3 * q + 1];
        float4 cc4 = y4[3 * q + 2];
        int4  mv = m4[q];
        int n0 = 4 * q;
        float yv[4][3] = {
            {a.x, a.y, a.z}, {a.w, b.x, b.y},
            {b.z, b.w, cc4.x}, {cc4.y, cc4.z, cc4.w}};
        int mm[4] = {mv.x, mv.y, mv.z, mv.w};
        #pragma unroll
        for (int k = 0; k < 4; k++) {
            if (mm[k] != 0) {
                float4 Z = g_Z[n0 + k];
                float dot = yv[k][0] * Z.x + yv[k][1] * Z.y + yv[k][2] * Z.z;
                float nz = sqrtf(Z.x * Z.x + Z.y * Z.y + Z.z * Z.z);
                float ny = sqrtf(yv[k][0] * yv[k][0] + yv[k][1] * yv[k][1] +
                                 yv[k][2] * yv[k][2]);
                float cosv = dot / (ny * nz);
                l += 1.0f - fabsf(cosv);
                float cl = fminf(1.0f, fmaxf(-1.0f, cosv));
                ang += acosf(cl) * 57.295779513082320877f;
                c += 1.0f;
            }
        }
    }
    int rem = N - (nq << 2);
    if (q < rem) {
        int i = (nq << 2) + q;
        if (mask[i] != 0) {
            float4 Z = g_Z[i];
            float y0 = y[3 * i], y1 = y[3 * i + 1], y2 = y[3 * i + 2];
            float dot = y0 * Z.x + y1 * Z.y + y2 * Z.z;
            float nz = sqrtf(Z.x * Z.x + Z.y * Z.y + Z.z * Z.z);
            float ny = sqrtf(y0 * y0 + y1 * y1 + y2 * y2);
            float cosv = dot / (ny * nz);
            l += 1.0f - fabsf(cosv);
            float cl = fminf(1.0f, fmaxf(-1.0f, cosv));
            ang += acosf(cl) * 57.295779513082320877f;
            c += 1.0f;
        }
    }

    #pragma unroll
    for (int o = 16; o > 0; o >>= 1) {
        l   += __shfl_down_sync(0xffffffffu, l,   o);
        ang += __shfl_down_sync(0xffffffffu, ang, o);
        c   += __shfl_down_sync(0xffffffffu, c,   o);
    }

    __shared__ float sl[8], sa_[8], sc[8];
    __shared__ bool is_last;
    int wid = threadIdx.x >> 5;
    int lid = threadIdx.x & 31;
    if (lid == 0) { sl[wid] = l; sa_[wid] = ang; sc[wid] = c; }
    __syncthreads();

    if (threadIdx.x == 0) {
        float bl = 0.f, ba = 0.f, bc = 0.f;
        int nwarp = (blockDim.x + 31) >> 5;
        for (int w = 0; w < nwarp; w++) { bl += sl[w]; ba += sa_[w]; bc += sc[w]; }
        atomicAdd(&g_acc[0], (double)bl);
        atomicAdd(&g_acc[1], (double)ba);
        atomicAdd(&g_acc[2], (double)bc);
        __threadfence();
        unsigned int done = atomicAdd(&g_done, 1u);
        is_last = (done == gridDim.x - 1);
    }
    __syncthreads();

    if (is_last && threadIdx.x == 0) {
        double cnt = g_acc[2];
        if (cnt < 1.0) cnt = 1.0;
        out[0] = (float)(g_acc[0] / cnt);
        out[1] = (float)(g_acc[1] / cnt);
        g_bar = 0u;                    // reset grid barrier for next replay
    }
}

// ---------------------------------------------------------------------------
extern "C" void kernel_launch(void* const* d_in, const int* in_sizes, int n_in,
                              void* d_out, int out_size) {
    const float* x    = (const float*)d_in[0];   // [N,3]
    const float* y    = (const float*)d_in[1];   // [N,3]
    const float* s    = (const float*)d_in[2];   // [N]
    const int*   ei   = (const int*)d_in[3];     // [2,E] int32
    const int*   mask = (const int*)d_in[4];     // [N]   int32 (bool)
    float* out = (float*)d_out;

    int N = in_sizes[2];
    int E = in_sizes[3] / 2;

    static int nsm = 0;
    if (nsm == 0) {
        cudaDeviceGetAttribute(&nsm, cudaDevAttrMultiProcessorCount, 0);
        if (nsm <= 0) nsm = 64;
    }
    // launch_bounds(256,6) guarantees 6 blocks/SM co-residency.
    pack_edge_kernel<<<nsm * 6, 256>>>(x, s, ei, N, E);

    const int TB = 256;
    int nq = (N + 3) / 4;
    node_kernel<<<(nq + TB - 1) / TB, TB>>>(y, mask, N, out);
}

// round 12
// speedup vs baseline: 1.0333x; 1.0333x over previous
#include <cuda_runtime.h>
#include <cstdint>

// ---------------------------------------------------------------------------
// CustomOrientationLoss (R12):
//   pack:  scalar 1 node/thr, grid 391  (measured 4.8us vs quad 5.7-6.2us)
//   edge:  1 edge/thr, occ 16 — UNCHANGED from R9 (best measured; LTS-bound)
//   node:  scalar 1 node/thr, TB=512, grid 196 — fixes grid=98 starvation
//          found in R11 profile (7.9us at occ 12%, traffic only ~1us worth)
// ---------------------------------------------------------------------------

#define NMAX 100000

__device__ float4 g_P[NMAX];        // (x0,x1,x2,s)
__device__ float4 g_Z[NMAX];        // accumulator (w unused)
__device__ double g_acc[3];         // sum(1-|cos|), sum(ang_deg), count
__device__ unsigned int g_done;     // last-block-done counter

// ---------------------------------------------------------------------------
// Scalar pack: warp-coalesced loads, aligned 16B stores. grid ~391.
__global__ void pack_kernel(const float* __restrict__ x,
                            const float* __restrict__ s,
                            int N) {
    int i = blockIdx.x * blockDim.x + threadIdx.x;
    if (i < N) {
        g_P[i] = make_float4(x[3 * i], x[3 * i + 1], x[3 * i + 2], s[i]);
        g_Z[i] = make_float4(0.f, 0.f, 0.f, 0.f);
    }
    if (i == 0) {
        g_acc[0] = 0.0; g_acc[1] = 0.0; g_acc[2] = 0.0;
        g_done = 0u;
    }
}

// ---------------------------------------------------------------------------
// 1 edge/thread, occ 16 (2048 threads/SM). Byte-identical to R9 best.
__global__ __launch_bounds__(128, 16)
void edge_kernel(const int* __restrict__ ei, int E) {
    int e = blockIdx.x * blockDim.x + threadIdx.x;
    if (e >= E) return;

    int a = __ldg(ei + e);
    int b = __ldg(ei + E + e);

    float4 Pa = __ldg(&g_P[a]);
    float4 Pb = __ldg(&g_P[b]);

    float ds = Pb.w - Pa.w;
    float cx = (Pb.x - Pa.x) * ds;
    float cy = (Pb.y - Pa.y) * ds;
    float cz = (Pb.z - Pa.z) * ds;

    asm volatile("red.global.add.v4.f32 [%0], {%1, %2, %3, %4};"
                 :: "l"((float*)&g_Z[a]), "f"(cx), "f"(cy), "f"(cz), "f"(0.0f) : "memory");
    asm volatile("red.global.add.v4.f32 [%0], {%1, %2, %3, %4};"
                 :: "l"((float*)&g_Z[b]), "f"(cx), "f"(cy), "f"(cz), "f"(0.0f) : "memory");
}

// ---------------------------------------------------------------------------
// Scalar node reduction (1 node/thread, TB=512 -> grid 196) + fused finalize.
__global__ void node_kernel(const float* __restrict__ y,
                            const int* __restrict__ mask,
                            int N, float* __restrict__ out) {
    int i = blockIdx.x * blockDim.x + threadIdx.x;

    float l = 0.f, ang = 0.f, c = 0.f;
    if (i < N && mask[i] != 0) {
        float4 Z = g_Z[i];
        float y0 = y[3 * i], y1 = y[3 * i + 1], y2 = y[3 * i + 2];
        float dot = y0 * Z.x + y1 * Z.y + y2 * Z.z;
        float nz = sqrtf(Z.x * Z.x + Z.y * Z.y + Z.z * Z.z);
        float ny = sqrtf(y0 * y0 + y1 * y1 + y2 * y2);
        float cosv = dot / (ny * nz);
        l = 1.0f - fabsf(cosv);
        float cl = fminf(1.0f, fmaxf(-1.0f, cosv));
        ang = acosf(cl) * 57.295779513082320877f;  // degrees
        c = 1.0f;
    }

    #pragma unroll
    for (int o = 16; o > 0; o >>= 1) {
        l   += __shfl_down_sync(0xffffffffu, l,   o);
        ang += __shfl_down_sync(0xffffffffu, ang, o);
        c   += __shfl_down_sync(0xffffffffu, c,   o);
    }

    __shared__ float sl[16], sa_[16], sc[16];
    __shared__ bool is_last;
    int wid = threadIdx.x >> 5;
    int lid = threadIdx.x & 31;
    if (lid == 0) { sl[wid] = l; sa_[wid] = ang; sc[wid] = c; }
    __syncthreads();

    if (threadIdx.x == 0) {
        float bl = 0.f, ba = 0.f, bc = 0.f;
        int nwarp = (blockDim.x + 31) >> 5;
        for (int w = 0; w < nwarp; w++) { bl += sl[w]; ba += sa_[w]; bc += sc[w]; }
        atomicAdd(&g_acc[0], (double)bl);
        atomicAdd(&g_acc[1], (double)ba);
        atomicAdd(&g_acc[2], (double)bc);
        __threadfence();
        unsigned int done = atomicAdd(&g_done, 1u);
        is_last = (done == gridDim.x - 1);
    }
    __syncthreads();

    if (is_last && threadIdx.x == 0) {
        double cnt = g_acc[2];
        if (cnt < 1.0) cnt = 1.0;
        out[0] = (float)(g_acc[0] / cnt);
        out[1] = (float)(g_acc[1] / cnt);
    }
}

// ---------------------------------------------------------------------------
extern "C" void kernel_launch(void* const* d_in, const int* in_sizes, int n_in,
                              void* d_out, int out_size) {
    const float* x    = (const float*)d_in[0];   // [N,3]
    const float* y    = (const float*)d_in[1];   // [N,3]
    const float* s    = (const float*)d_in[2];   // [N]
    const int*   ei   = (const int*)d_in[3];     // [2,E] int32
    const int*   mask = (const int*)d_in[4];     // [N]   int32 (bool)
    float* out = (float*)d_out;

    int N = in_sizes[2];
    int E = in_sizes[3] / 2;

    const int TBP = 256;                              // pack: grid ~391
    pack_kernel<<<(N + TBP - 1) / TBP, TBP>>>(x, s, N);

    const int TBE = 128;                              // edge: grid 25000
    edge_kernel<<<(E + TBE - 1) / TBE, TBE>>>(ei, E);

    const int TBN = 512;                              // node: grid ~196
    node_kernel<<<(N + TBN - 1) / TBN, TBN>>>(y, mask, N, out);
}